// round 14
// baseline (speedup 1.0000x reference)
#include <cuda_runtime.h>
#include <cuda_bf16.h>

#define DIM 128
#define MAX_TYP 4096

// Scratch: window sums, per-half-type partial edge sums, validity flag.
__device__ float g_W[MAX_TYP * DIM];             // 2 MB
__device__ float g_part[2 * MAX_TYP * DIM];      // 4 MB
__device__ int   g_flag;

// ---------------------------------------------------------------------------
// K1 (deg2==64): 2 blocks per type; block b = type b/2, half b&1 (32 edges).
// 4 warps x 8 edges, front-batched row loads, block reduce, 512B partial out.
// Short serial path: no epilogue row load, no final output store.
// ---------------------------------------------------------------------------
__global__ void __launch_bounds__(128, 8) sub2_partial_kernel(
        const float* __restrict__ emb,
        const int* __restrict__ sub2_row,
        const int* __restrict__ left_specific,
        int deg2) {
    __shared__ float4 red[4][32];

    const int b    = blockIdx.x;
    const int c    = b >> 1;
    const int h    = b & 1;
    const int w    = threadIdx.x >> 5;
    const int lane = threadIdx.x & 31;

    if (b == 0 && threadIdx.x == 0) g_flag = 1;   // runs before K2 reads it

    // Lanes 0-7: resolve this warp's 8 row indices.
    int row_l = 0;
    if (lane < 8)
        row_l = __ldg(left_specific +
                      __ldg(sub2_row + (size_t)c * deg2 + h * 32 + w * 8 + lane));

    int rows[8];
#pragma unroll
    for (int i = 0; i < 8; ++i)
        rows[i] = __shfl_sync(0xffffffffu, row_l, i);

    float4 v[8];
#pragma unroll
    for (int i = 0; i < 8; ++i)
        v[i] = __ldg((const float4*)(emb + (size_t)rows[i] * DIM) + lane);

    float4 acc = v[0];
#pragma unroll
    for (int i = 1; i < 8; ++i) {
        acc.x += v[i].x; acc.y += v[i].y; acc.z += v[i].z; acc.w += v[i].w;
    }
    red[w][lane] = acc;
    __syncthreads();

    if (w == 0) {
        float4 s = red[0][lane];
#pragma unroll
        for (int k = 1; k < 4; ++k) {
            const float4 t = red[k][lane];
            s.x += t.x; s.y += t.y; s.z += t.z; s.w += t.w;
        }
        ((float4*)(g_part + (size_t)b * DIM))[lane] = s;
    }
}

// ---------------------------------------------------------------------------
// K2 (deg2==64, deg3==4): fused finalize + window. Global warp g:
//   g in [0, n_typ):      W[g] = sum_{j<4} row(g+j mod n_typ), where
//                         row(t) = emb[right_common[t]] + (n_ent-deg2)
//                                + part[2t] + part[2t+1]
//                         valid iff left_common[t]==right_common[t] (checked;
//                         failure clears g_flag -> sub3 falls back).
//   g in [n_typ, 2n_typ): finalize out[right_common[g-n_typ]].
// ---------------------------------------------------------------------------
__global__ void finalize_window_kernel(
        const float* __restrict__ emb,
        const int* __restrict__ left_common,
        const int* __restrict__ right_common,
        float* __restrict__ out,
        int n_ent, int n_typ, int deg2) {
    const int g    = blockIdx.x * (blockDim.x >> 5) + (threadIdx.x >> 5);
    const int lane = threadIdx.x & 31;
    const float a2 = (float)(n_ent - deg2);

    if (g < n_typ) {
        // lanes 0-3: check + fetch rc for window positions.
        int rc_l = 0; bool okl = true;
        if (lane < 4) {
            int tt = g + lane; if (tt >= n_typ) tt -= n_typ;
            rc_l = __ldg(right_common + tt);
            okl  = (__ldg(left_common + tt) == rc_l);
        }
        const bool ok = __all_sync(0xffffffffu, okl);
        if (!ok) {
            if (lane == 0) g_flag = 0;
            return;
        }
        float4 acc = make_float4(4.0f * a2, 4.0f * a2, 4.0f * a2, 4.0f * a2);
#pragma unroll
        for (int j = 0; j < 4; ++j) {
            int tt = g + j; if (tt >= n_typ) tt -= n_typ;
            const int    rc = __shfl_sync(0xffffffffu, rc_l, j);
            const float4 e  = __ldg((const float4*)(emb + (size_t)rc * DIM) + lane);
            const float4 p0 = ((const float4*)(g_part + (size_t)(2 * tt) * DIM))[lane];
            const float4 p1 = ((const float4*)(g_part + (size_t)(2 * tt + 1) * DIM))[lane];
            acc.x += e.x + p0.x + p1.x;
            acc.y += e.y + p0.y + p1.y;
            acc.z += e.z + p0.z + p1.z;
            acc.w += e.w + p0.w + p1.w;
        }
        ((float4*)(g_W + (size_t)g * DIM))[lane] = acc;
    } else if (g < 2 * n_typ) {
        const int c  = g - n_typ;
        const int rc = __ldg(right_common + c);
        const float4 e  = __ldg((const float4*)(emb + (size_t)rc * DIM) + lane);
        const float4 p0 = ((const float4*)(g_part + (size_t)(2 * c) * DIM))[lane];
        const float4 p1 = ((const float4*)(g_part + (size_t)(2 * c + 1) * DIM))[lane];
        float4 r;
        r.x = e.x + p0.x + p1.x + a2;
        r.y = e.y + p0.y + p1.y + a2;
        r.z = e.z + p0.z + p1.z + a2;
        r.w = e.w + p0.w + p1.w + a2;
        ((float4*)(out + (size_t)rc * DIM))[lane] = r;
    }
}

// ---------------------------------------------------------------------------
// Generic sub2 (any deg2): finalizes out[rc] directly (old path).
// ---------------------------------------------------------------------------
__global__ void sub2_kernel(const float* __restrict__ emb,
                            const int* __restrict__ sub2_row,
                            const int* __restrict__ left_specific,
                            const int* __restrict__ right_common,
                            float* __restrict__ out,
                            int n_ent, int deg2) {
    extern __shared__ char smem_raw[];
    int*    rows = (int*)smem_raw;
    float4* red  = (float4*)(smem_raw + ((deg2 * 4 + 127) & ~127));

    const int c     = blockIdx.x;
    const int w     = threadIdx.x >> 5;
    const int lane  = threadIdx.x & 31;
    const int nwarp = blockDim.x >> 5;

    for (int j = threadIdx.x; j < deg2; j += blockDim.x)
        rows[j] = left_specific[__ldg(sub2_row + (size_t)c * deg2 + j)];
    __syncthreads();

    float4 acc = make_float4(0.f, 0.f, 0.f, 0.f);
    for (int j = w; j < deg2; j += nwarp) {
        const float4 v = __ldg((const float4*)(emb + (size_t)rows[j] * DIM) + lane);
        acc.x += v.x; acc.y += v.y; acc.z += v.z; acc.w += v.w;
    }
    red[w * 32 + lane] = acc;
    __syncthreads();

    if (w == 0) {
        float4 s = red[lane];
#pragma unroll
        for (int k = 1; k < 8; ++k) {
            const float4 v = red[k * 32 + lane];
            s.x += v.x; s.y += v.y; s.z += v.z; s.w += v.w;
        }
        const int   rc = right_common[c];
        const float a  = (float)(n_ent - deg2);
        const float4 e = __ldg((const float4*)(emb + (size_t)rc * DIM) + lane);
        float4 r;
        r.x = e.x + s.x + a; r.y = e.y + s.y + a;
        r.z = e.z + s.z + a; r.w = e.w + s.w + a;
        ((float4*)(out + (size_t)rc * DIM) + lane)[0] = r;
    }
}

// Old window kernel (reads finalized out rows) for the generic-deg2 path.
__global__ void window_kernel(const float* __restrict__ out,
                              const int* __restrict__ left_common,
                              int n_typ) {
    const int t    = blockIdx.x * (blockDim.x >> 5) + (threadIdx.x >> 5);
    const int lane = threadIdx.x & 31;
    if (t == 0 && lane == 0) g_flag = 1;
    if (t >= n_typ) return;
    float4 acc = make_float4(0.f, 0.f, 0.f, 0.f);
#pragma unroll
    for (int j = 0; j < 4; ++j) {
        int tt = t + j;
        if (tt >= n_typ) tt -= n_typ;
        const int node = __ldg(left_common + tt);
        const float4 v = __ldg((const float4*)(out + (size_t)node * DIM) + lane);
        acc.x += v.x; acc.y += v.y; acc.z += v.z; acc.w += v.w;
    }
    ((float4*)(g_W + (size_t)t * DIM))[lane] = acc;
}

// ---------------------------------------------------------------------------
// sub3 (deg3==4): 2 entities/warp, register-lean (256,8). Window check via
// shuffles AND g_flag; 1 W-gather per entity on the fast path; direct
// gathers of finalized out type rows otherwise. Entity stream __ldcs/__stcs.
// ---------------------------------------------------------------------------
__global__ void __launch_bounds__(256, 8) sub3_kernel_d2w(
        const float* __restrict__ emb,
        const int* __restrict__ sub3_row,
        const int* __restrict__ left_common,
        const int* __restrict__ right_specific,
        float* out,
        int n_ent, int n_typ) {
    const int gw   = blockIdx.x * 8 + (threadIdx.x >> 5);
    const int lane = threadIdx.x & 31;
    const int base = gw * 2;
    if (base >= n_ent) return;
    const bool two = (base + 1 < n_ent);

    int ridx_l = 0;
    if (lane < 8 && base + (lane >> 2) < n_ent)
        ridx_l = __ldg(sub3_row + (size_t)base * 4 + lane);
    int rs_l = 0;
    if (lane >= 8 && lane < 10 && base + (lane - 8) < n_ent)
        rs_l = __ldg(right_specific + base + (lane - 8));

    const int rs0 = __shfl_sync(0xffffffffu, rs_l, 8);
    const int rs1 = __shfl_sync(0xffffffffu, rs_l, 9);

    float4 e0 = __ldcs((const float4*)(emb + (size_t)rs0 * DIM) + lane);
    float4 e1 = make_float4(0.f, 0.f, 0.f, 0.f);
    if (two)
        e1 = __ldcs((const float4*)(emb + (size_t)rs1 * DIM) + lane);

    const int flag = g_flag;
    const int b0 = __shfl_sync(0xffffffffu, ridx_l, 0);
    const int b1 = __shfl_sync(0xffffffffu, ridx_l, 4);
    bool ok0 = flag && (b0 >= 0) && (b0 < n_typ);
    bool ok1 = flag && (b1 >= 0) && (b1 < n_typ);
#pragma unroll
    for (int j = 1; j < 4; ++j) {
        int x0 = b0 + j; if (x0 >= n_typ) x0 -= n_typ;
        int x1 = b1 + j; if (x1 >= n_typ) x1 -= n_typ;
        ok0 = ok0 && (__shfl_sync(0xffffffffu, ridx_l, j)     == x0);
        ok1 = ok1 && (__shfl_sync(0xffffffffu, ridx_l, 4 + j) == x1);
    }

    float4 a0, a1;
    if (ok0) {
        a0 = ((const float4*)(g_W + (size_t)b0 * DIM))[lane];
    } else {
        a0 = make_float4(0.f, 0.f, 0.f, 0.f);
#pragma unroll
        for (int j = 0; j < 4; ++j) {
            const int node = __ldg(left_common + __shfl_sync(0xffffffffu, ridx_l, j));
            const float4 v = __ldg((const float4*)(out + (size_t)node * DIM) + lane);
            a0.x += v.x; a0.y += v.y; a0.z += v.z; a0.w += v.w;
        }
    }
    if (two) {
        if (ok1) {
            a1 = ((const float4*)(g_W + (size_t)b1 * DIM))[lane];
        } else {
            a1 = make_float4(0.f, 0.f, 0.f, 0.f);
#pragma unroll
            for (int j = 0; j < 4; ++j) {
                const int node = __ldg(left_common + __shfl_sync(0xffffffffu, ridx_l, 4 + j));
                const float4 v = __ldg((const float4*)(out + (size_t)node * DIM) + lane);
                a1.x += v.x; a1.y += v.y; a1.z += v.z; a1.w += v.w;
            }
        }
    }

    const float addc = (float)(n_typ - 4);
    const float inv  = 0.2f;

    float4 o0;
    o0.x = e0.x * (1.0f - (a0.x + addc) * inv);
    o0.y = e0.y * (1.0f - (a0.y + addc) * inv);
    o0.z = e0.z * (1.0f - (a0.z + addc) * inv);
    o0.w = e0.w * (1.0f - (a0.w + addc) * inv);
    __stcs((float4*)(out + (size_t)rs0 * DIM) + lane, o0);

    if (two) {
        float4 o1;
        o1.x = e1.x * (1.0f - (a1.x + addc) * inv);
        o1.y = e1.y * (1.0f - (a1.y + addc) * inv);
        o1.z = e1.z * (1.0f - (a1.z + addc) * inv);
        o1.w = e1.w * (1.0f - (a1.w + addc) * inv);
        __stcs((float4*)(out + (size_t)rs1 * DIM) + lane, o1);
    }
}

// Generic fallback (any deg3), one warp per entity.
__global__ void sub3_kernel_gen(const float* __restrict__ emb,
                                const int* __restrict__ sub3_row,
                                const int* __restrict__ left_common,
                                const int* __restrict__ right_specific,
                                float* out,
                                int n_ent, int n_typ, int deg3) {
    const int gw   = (int)((blockIdx.x * (size_t)blockDim.x + threadIdx.x) >> 5);
    const int lane = threadIdx.x & 31;
    if (gw >= n_ent) return;

    const float addc = (float)(n_typ - deg3);
    const float inv  = 1.0f / (float)(1 + deg3);

    float4 acc = make_float4(0.f, 0.f, 0.f, 0.f);
    const int* rbase = sub3_row + (size_t)gw * deg3;
    for (int j = 0; j < deg3; ++j) {
        const int node = left_common[__ldg(rbase + j)];
        const float4 v = __ldg((const float4*)(out + (size_t)node * DIM) + lane);
        acc.x += v.x; acc.y += v.y; acc.z += v.z; acc.w += v.w;
    }
    const int   rs = right_specific[gw];
    const float4 e = __ldcs((const float4*)(emb + (size_t)rs * DIM) + lane);
    float4 r;
    r.x = e.x * (1.0f - (acc.x + addc) * inv);
    r.y = e.y * (1.0f - (acc.y + addc) * inv);
    r.z = e.z * (1.0f - (acc.z + addc) * inv);
    r.w = e.w * (1.0f - (acc.w + addc) * inv);
    __stcs((float4*)(out + (size_t)rs * DIM) + lane, r);
}

extern "C" void kernel_launch(void* const* d_in, const int* in_sizes, int n_in,
                              void* d_out, int out_size) {
    const float* emb            = (const float*)d_in[0];
    const int*   sub2_row       = (const int*)d_in[1];
    const int*   sub3_row       = (const int*)d_in[3];
    const int*   left_specific  = (const int*)d_in[5];
    const int*   right_common   = (const int*)d_in[6];
    const int*   left_common    = (const int*)d_in[7];
    const int*   right_specific = (const int*)d_in[8];
    float*       out            = (float*)d_out;

    const int n_ent = in_sizes[5];                 // 200000
    const int n_typ = in_sizes[7];                 // 1000
    const int deg2  = in_sizes[1] / n_typ;         // 64
    const int deg3  = in_sizes[3] / n_ent;         // 4

    const bool fast = (deg2 == 64) && (deg3 == 4) && (n_typ <= MAX_TYP);

    if (fast) {
        // K1: partial edge sums (2 blocks per type, short critical path).
        sub2_partial_kernel<<<2 * n_typ, 128>>>(emb, sub2_row, left_specific, deg2);
        // K2: fused type-row finalize + window sums from partials.
        finalize_window_kernel<<<(2 * n_typ + 7) / 8, 256>>>(
            emb, left_common, right_common, out, n_ent, n_typ, deg2);
        // K3: entity stream.
        const int ent_per_block = 8 * 2;
        const int blocks = (n_ent + ent_per_block - 1) / ent_per_block;
        sub3_kernel_d2w<<<blocks, 256>>>(
            emb, sub3_row, left_common, right_specific, out, n_ent, n_typ);
    } else {
        const int smem = ((deg2 * 4 + 127) & ~127) + 8 * 32 * (int)sizeof(float4);
        sub2_kernel<<<n_typ, 256, smem>>>(
            emb, sub2_row, left_specific, right_common, out, n_ent, deg2);
        if (deg3 == 4 && n_typ <= MAX_TYP) {
            window_kernel<<<(n_typ + 3) / 4, 128>>>(out, left_common, n_typ);
            const int ent_per_block = 8 * 2;
            const int blocks = (n_ent + ent_per_block - 1) / ent_per_block;
            sub3_kernel_d2w<<<blocks, 256>>>(
                emb, sub3_row, left_common, right_specific, out, n_ent, n_typ);
        } else {
            const int wpb = 8;
            const int blocks = (n_ent + wpb - 1) / wpb;
            sub3_kernel_gen<<<blocks, wpb * 32>>>(
                emb, sub3_row, left_common, right_specific, out, n_ent, n_typ, deg3);
        }
    }
}